// round 13
// baseline (speedup 1.0000x reference)
#include <cuda_runtime.h>

#define BATCH 128
#define NT 512
#define S_BYTES (996 * 52 * 4)

__device__ float g_partials[BATCH];
__device__ float g_wcol[50];
__device__ unsigned int g_count = 0;
__device__ int g_wflag = 0;

__device__ __forceinline__ float warp_sum(float v) {
#pragma unroll
    for (int o = 16; o; o >>= 1) v += __shfl_down_sync(0xffffffffu, v, o);
    return v;
}

// grid = BATCH+1. Blocks 0..127: one batch element. Block 128: w_cat column norms.
__global__ __launch_bounds__(NT, 1)
void loss_main(const float* __restrict__ input,
               const float* __restrict__ target,
               const float* __restrict__ normals,
               const float* __restrict__ param_mean,
               const float* __restrict__ param_std,
               const float* __restrict__ u,
               const float* __restrict__ w_shp,
               const float* __restrict__ w_exp,
               const int*   __restrict__ keyindex,
               const int*   __restrict__ ridx_w,
               const int*   __restrict__ ridx_v,
               float* __restrict__ out)
{
    const int tid  = threadIdx.x;
    const int lane = tid & 31;
    const int wid  = tid >> 5;

    // ============ dedicated block: batch-independent w_cat column norms ============
    if (blockIdx.x == BATCH) {
        __shared__ int srw[600];
        __shared__ float cpart[16][50];
        for (int l = tid; l < 600; l += NT) {
            int j = l / 3, c = l - 3 * j;
            int vid = (j < 68) ? keyindex[j] : ridx_w[j - 68];
            srw[l] = 3 * vid + c;
        }
        __syncthreads();
        float a1 = 0.f, a2 = 0.f;
        const int c1 = lane;
        const int c2 = lane + 32;
#pragma unroll 2
        for (int rr = wid; rr < 600; rr += 16) {
            size_t r = (size_t)srw[rr];
            float v1 = w_shp[r * 40 + c1];
            a1 += v1 * v1;
            if (c2 < 50) {
                float v2 = (c2 < 40) ? w_shp[r * 40 + c2] : w_exp[r * 10 + (c2 - 40)];
                a2 += v2 * v2;
            }
        }
        cpart[wid][c1] = a1;
        if (c2 < 50) cpart[wid][c2] = a2;
        __syncthreads();
        if (tid < 50) {
            float s = 0.f;
#pragma unroll
            for (int w = 0; w < 16; w++) s += cpart[w][tid];
            g_wcol[tid] = sqrtf(s);
        }
        __threadfence();
        __syncthreads();
        if (tid == 0) atomicExch(&g_wflag, 1);
        return;
    }

    // ============ per-batch block ============
    const int n = blockIdx.x;

    extern __shared__ float S[];       // S[row*52 + c]: c0..49 = wshp|wexp, c50 = u, c51 pad
    __shared__ float sp[62], spg[62];
    __shared__ int   sidx[332];        // [0,68) key | [68,200) ridx_w | [200,332) ridx_v
    __shared__ int   srow[996];        // global row index (3*vid+cc) per S row
    __shared__ float bv[600], bvg[600];
    __shared__ float tn_w[16][3];
    __shared__ float tnsq[3];
    __shared__ float sncol[4][68];     // per-warp normals colsum partials (warps 12..15)
    __shared__ float4 vt4[200], vtg4[200];   // .w = |xyz|^2
    __shared__ float wsum[16];
    __shared__ int   s_last;

    // ---- 0a. params + indices ----
    if (tid < 62) {
        float st = param_std[tid], mn = param_mean[tid];
        sp[tid]  = input [n * 62 + tid] * st + mn;
        spg[tid] = target[n * 62 + tid] * st + mn;
    } else if (tid >= 64 && tid < 396) {
        int j = tid - 64;
        sidx[j] = (j < 68) ? keyindex[j] : (j < 200 ? ridx_w[j - 68] : ridx_v[j - 200]);
    }
    __syncthreads();

    // ---- 0b. per-row global addresses ----
    // S rows: [0,204) keypoints | [204,600) ridx_v | [600,996) ridx_w
    for (int i = tid; i < 996; i += NT) {
        int vid, cc;
        if (i < 204)      { vid = sidx[i / 3];                       cc = i % 3; }
        else if (i < 600) { int m = i - 204; vid = sidx[200 + m / 3]; cc = m % 3; }
        else              { int m = i - 600; vid = sidx[68 + m / 3];  cc = m % 3; }
        srow[i] = 3 * vid + cc;
    }
    __syncthreads();

    // ---- 1. coalesced copy (warps 0..11) ; warps 12..15: normals column sums ----
    if (wid < 12) {
        const int NTC = 384;
        const float4* w4 = (const float4*)w_shp;
#pragma unroll 2
        for (int e = tid; e < 9960; e += NTC) {
            int row = e / 10, f = e - 10 * row;
            float4 v = w4[(size_t)srow[row] * 10 + f];
            *(float4*)(S + row * 52 + 4 * f) = v;
        }
        const float2* e2 = (const float2*)w_exp;
#pragma unroll 2
        for (int e = tid; e < 4980; e += NTC) {
            int row = e / 5, f = e - 5 * row;
            float2 v = e2[(size_t)srow[row] * 5 + f];
            *(float2*)(S + row * 52 + 40 + 2 * f) = v;
        }
        for (int i = tid; i < 996; i += NTC) {
            S[i * 52 + 50] = u[srow[i]];
        }
    } else {
        // warps 12..15: each sums rows i = (wid-12), (wid-12)+4, ... (17 rows)
        int w4i = wid - 12;
        float ns0 = 0.f, ns1 = 0.f, ns2 = 0.f;
        const float* nb = normals + (size_t)n * (68 * 68);
#pragma unroll 4
        for (int i = w4i; i < 68; i += 4) {
            const float* rowp = nb + i * 68;
            ns0 += rowp[lane];
            ns1 += rowp[lane + 32];
            if (lane < 4) ns2 += rowp[lane + 64];
        }
        sncol[w4i][lane] = ns0;
        sncol[w4i][lane + 32] = ns1;   // overwritten below for lanes>=36? no: cols 32..63
        __syncwarp();
        if (lane < 4) sncol[w4i][lane + 64] = ns2;
    }
    __syncthreads();

    // ---- 2. dot phase from SMEM: 996 row jobs (conflict-free LDS.128) ----
    float tn0 = 0.f, tn1 = 0.f, tn2 = 0.f;
#pragma unroll 1
    for (int l = tid; l < 996; l += NT) {
        const float4* Sr = (const float4*)(S + l * 52);
        if (l < 600) {
            // dual pred+gt
            float pa = 0.f, pb = 0.f, ga = 0.f, gb = 0.f;
#pragma unroll
            for (int f = 0; f < 12; f++) {
                float4 x = Sr[f];
                pa += x.x * sp [12 + 4*f] + x.z * sp [14 + 4*f];
                pb += x.y * sp [13 + 4*f] + x.w * sp [15 + 4*f];
                ga += x.x * spg[12 + 4*f] + x.z * spg[14 + 4*f];
                gb += x.y * spg[13 + 4*f] + x.w * spg[15 + 4*f];
            }
            float4 t = Sr[12];           // x=col48, y=col49, z=u, w=pad
            pa += t.x * sp [60] + t.z;   pb += t.y * sp [61];
            ga += t.x * spg[60] + t.z;   gb += t.y * spg[61];
            float s = pa + pb, g = ga + gb;
            bv[l] = s; bvg[l] = g;
            if (l < 204) {
                float s2 = s * s;
                int c3 = l % 3;
                if (c3 == 0) tn0 += s2; else if (c3 == 1) tn1 += s2; else tn2 += s2;
            }
        } else {
            // pred-only (ridx_w rows) -> tn
            float pa = 0.f, pb = 0.f;
#pragma unroll
            for (int f = 0; f < 12; f++) {
                float4 x = Sr[f];
                pa += x.x * sp[12 + 4*f] + x.z * sp[14 + 4*f];
                pb += x.y * sp[13 + 4*f] + x.w * sp[15 + 4*f];
            }
            float4 t = Sr[12];
            pa += t.x * sp[60] + t.z;
            pb += t.y * sp[61];
            float s = pa + pb;
            float s2 = s * s;
            int c3 = l % 3;
            if (c3 == 0) tn0 += s2; else if (c3 == 1) tn1 += s2; else tn2 += s2;
        }
    }
    tn0 = warp_sum(tn0); tn1 = warp_sum(tn1); tn2 = warp_sum(tn2);
    if (lane == 0) { tn_w[wid][0] = tn0; tn_w[wid][1] = tn1; tn_w[wid][2] = tn2; }
    __syncthreads();

    // ---- 3. fold tn, rotate verts (+|v|^2 in .w), wait for wcol flag ----
    if (tid < 3) {
        float s = 0.f;
#pragma unroll
        for (int w = 0; w < 16; w++) s += tn_w[w][tid];
        tnsq[tid] = s;
    }
    if (tid >= 256 && tid < 456) {
        int t = tid - 256;
        float b0 = bv [3*t], b1 = bv [3*t+1], b2 = bv [3*t+2];
        float c0 = bvg[3*t], c1 = bvg[3*t+1], c2 = bvg[3*t+2];
        float4 o1, o2;
        o1.x = sp [0]*b0 + sp [1]*b1 + sp [2]*b2 + sp [3];
        o1.y = sp [4]*b0 + sp [5]*b1 + sp [6]*b2 + sp [7];
        o1.z = sp [8]*b0 + sp [9]*b1 + sp[10]*b2 + sp[11];
        o1.w = o1.x*o1.x + o1.y*o1.y + o1.z*o1.z;
        o2.x = spg[0]*c0 + spg[1]*c1 + spg[2]*c2 + spg[3];
        o2.y = spg[4]*c0 + spg[5]*c1 + spg[6]*c2 + spg[7];
        o2.z = spg[8]*c0 + spg[9]*c1 + spg[10]*c2 + spg[11];
        o2.w = o2.x*o2.x + o2.y*o2.y + o2.z*o2.z;
        vt4[t] = o1; vtg4[t] = o2;
    }
    if (tid == 32) {
        while (atomicAdd(&g_wflag, 0) == 0) __nanosleep(64);
    }
    __syncthreads();
    __threadfence();  // acquire for g_wcol

    // ---- 4. warp0: weights+wpdc; chamfer tid 96..195 & 256..355; warp 15: nwl ----
    float tot = 0.f;
    if (wid == 0) {
        int p1 = lane, p2 = lane + 32;
        float wj1, wj2 = 0.f;
        {
            float pd = fabsf(sp[p1] - spg[p1]);
            if (p1 < 11) {
                int cc = p1 & 3;
                float sc = (cc < 3) ? sqrtf(tnsq[cc]) : 14.142135623730951f;
                wj1 = pd * sc + 1e-6f;
            } else if (p1 == 11) wj1 = 1e-6f;
            else wj1 = 0.00057339936f * pd * g_wcol[p1 - 12] + 1e-6f;
        }
        if (p2 < 62) {
            float pd = fabsf(sp[p2] - spg[p2]);
            wj2 = 0.00057339936f * pd * g_wcol[p2 - 12] + 1e-6f;
        }
        float m = fmaxf(wj1, wj2);
#pragma unroll
        for (int o = 16; o; o >>= 1) m = fmaxf(m, __shfl_xor_sync(0xffffffffu, m, o));
        float wpdc = 0.f;
        if (p1 != 11) {
            float d = input[n * 62 + p1] - target[n * 62 + p1];
            wpdc += (wj1 / m) * d * d;
        }
        if (p2 < 62) {
            float d = input[n * 62 + p2] - target[n * 62 + p2];
            wpdc += (wj2 / m) * d * d;
        }
        tot += wpdc * (1.f / (128.f * 62.f));
    } else if (tid >= 96 && tid < 196) {
        int t = tid - 96;
        float4 X1 = vtg4[t], X2 = vtg4[t + 100];
        float x1x = -2.f*X1.x, x1y = -2.f*X1.y, x1z = -2.f*X1.z;
        float x2x = -2.f*X2.x, x2y = -2.f*X2.y, x2z = -2.f*X2.z;
        float m1a = 3.4e38f, m1b = 3.4e38f, m2a = 3.4e38f, m2b = 3.4e38f;
#pragma unroll 4
        for (int k = 0; k < 200; k += 2) {
            float4 a = vt4[k], b = vt4[k + 1];
            m1a = fminf(m1a, fmaf(x1x, a.x, fmaf(x1y, a.y, fmaf(x1z, a.z, a.w))));
            m1b = fminf(m1b, fmaf(x1x, b.x, fmaf(x1y, b.y, fmaf(x1z, b.z, b.w))));
            m2a = fminf(m2a, fmaf(x2x, a.x, fmaf(x2y, a.y, fmaf(x2z, a.z, a.w))));
            m2b = fminf(m2b, fmaf(x2x, b.x, fmaf(x2y, b.y, fmaf(x2z, b.z, b.w))));
        }
        float d1 = X1.w + fminf(m1a, m1b);
        float d2 = X2.w + fminf(m2a, m2b);
        tot += (d1 + d2) * (3.f * 0.001f / (128.f * 200.f));
    } else if (tid >= 256 && tid < 356) {
        int t = tid - 256;
        float4 Y1 = vt4[t], Y2 = vt4[t + 100];
        float y1x = -2.f*Y1.x, y1y = -2.f*Y1.y, y1z = -2.f*Y1.z;
        float y2x = -2.f*Y2.x, y2y = -2.f*Y2.y, y2z = -2.f*Y2.z;
        float m1a = 3.4e38f, m1b = 3.4e38f, m2a = 3.4e38f, m2b = 3.4e38f;
#pragma unroll 4
        for (int k = 0; k < 200; k += 2) {
            float4 a = vtg4[k], b = vtg4[k + 1];
            m1a = fminf(m1a, fmaf(y1x, a.x, fmaf(y1y, a.y, fmaf(y1z, a.z, a.w))));
            m1b = fminf(m1b, fmaf(y1x, b.x, fmaf(y1y, b.y, fmaf(y1z, b.z, b.w))));
            m2a = fminf(m2a, fmaf(y2x, a.x, fmaf(y2y, a.y, fmaf(y2z, a.z, a.w))));
            m2b = fminf(m2b, fmaf(y2x, b.x, fmaf(y2y, b.y, fmaf(y2z, b.z, b.w))));
        }
        float d1 = Y1.w + fminf(m1a, m1b);
        float d2 = Y2.w + fminf(m2a, m2b);
        tot += (d1 + d2) * (3.f * 0.001f / (128.f * 200.f));
    } else if (wid == 15) {
        const float k_nwl = 3.f * 0.001f / (128.f * 68.f * 3.f);
        {
            int t = lane;
            float s = sncol[0][t] + sncol[1][t] + sncol[2][t] + sncol[3][t];
            float d0 = vtg4[t].x - vt4[t].x;
            float d1 = vtg4[t].y - vt4[t].y;
            float d2 = vtg4[t].z - vt4[t].z;
            tot += s * (d0*d0 + d1*d1 + d2*d2) * k_nwl;
        }
        {
            int t = lane + 32;
            float s = sncol[0][t] + sncol[1][t] + sncol[2][t] + sncol[3][t];
            float d0 = vtg4[t].x - vt4[t].x;
            float d1 = vtg4[t].y - vt4[t].y;
            float d2 = vtg4[t].z - vt4[t].z;
            tot += s * (d0*d0 + d1*d1 + d2*d2) * k_nwl;
        }
        if (lane < 4) {
            int t = lane + 64;
            float s = sncol[0][t] + sncol[1][t] + sncol[2][t] + sncol[3][t];
            float d0 = vtg4[t].x - vt4[t].x;
            float d1 = vtg4[t].y - vt4[t].y;
            float d2 = vtg4[t].z - vt4[t].z;
            tot += s * (d0*d0 + d1*d1 + d2*d2) * k_nwl;
        }
    }

    // ---- 5. block reduce + finalize (fixed order -> deterministic) ----
    tot = warp_sum(tot);
    if (lane == 0) wsum[wid] = tot;
    __syncthreads();
    if (tid == 0) {
        float b = 0.f;
#pragma unroll
        for (int w = 0; w < 16; w++) b += wsum[w];
        g_partials[n] = b;
        __threadfence();
        unsigned int old = atomicAdd(&g_count, 1u);
        s_last = (old == BATCH - 1);
    }
    __syncthreads();
    if (s_last) {
        __threadfence();
        if (wid == 0) {
            float v = g_partials[lane] + g_partials[lane + 32]
                    + g_partials[lane + 64] + g_partials[lane + 96];
#pragma unroll
            for (int o = 16; o; o >>= 1) v += __shfl_down_sync(0xffffffffu, v, o);
            if (lane == 0) { out[0] = v; g_count = 0; g_wflag = 0; }
        }
    }
}

extern "C" void kernel_launch(void* const* d_in, const int* in_sizes, int n_in,
                              void* d_out, int out_size)
{
    (void)in_sizes; (void)n_in; (void)out_size;
    cudaFuncSetAttribute(loss_main, cudaFuncAttributeMaxDynamicSharedMemorySize, S_BYTES);
    loss_main<<<BATCH + 1, NT, S_BYTES>>>(
        (const float*)d_in[0],   // input
        (const float*)d_in[1],   // target
        (const float*)d_in[2],   // normals
        (const float*)d_in[3],   // param_mean
        (const float*)d_in[4],   // param_std
        (const float*)d_in[5],   // u
        (const float*)d_in[6],   // w_shp
        (const float*)d_in[7],   // w_exp
        (const int*)d_in[8],     // keyindex
        (const int*)d_in[9],     // resample_idx_w
        (const int*)d_in[10],    // resample_idx_v
        (float*)d_out);
}

// round 14
// speedup vs baseline: 1.0227x; 1.0227x over previous
#include <cuda_runtime.h>

#define BATCH 128
#define NT 512
#define S_BYTES (996 * 52 * 4)

__device__ float g_partials[BATCH];
__device__ float g_wcol[50];
__device__ unsigned int g_count = 0;
__device__ int g_wflag = 0;

__device__ __forceinline__ float warp_sum(float v) {
#pragma unroll
    for (int o = 16; o; o >>= 1) v += __shfl_down_sync(0xffffffffu, v, o);
    return v;
}

// grid = BATCH+1. Blocks 0..127: one batch element. Block 128: w_cat column norms.
__global__ __launch_bounds__(NT, 1)
void loss_main(const float* __restrict__ input,
               const float* __restrict__ target,
               const float* __restrict__ normals,
               const float* __restrict__ param_mean,
               const float* __restrict__ param_std,
               const float* __restrict__ u,
               const float* __restrict__ w_shp,
               const float* __restrict__ w_exp,
               const int*   __restrict__ keyindex,
               const int*   __restrict__ ridx_w,
               const int*   __restrict__ ridx_v,
               float* __restrict__ out)
{
    const int tid  = threadIdx.x;
    const int lane = tid & 31;
    const int wid  = tid >> 5;

    // ============ dedicated block: batch-independent w_cat column norms ============
    if (blockIdx.x == BATCH) {
        __shared__ int srw[600];
        __shared__ float cpart[16][50];
        for (int l = tid; l < 600; l += NT) {
            int j = l / 3, c = l - 3 * j;
            int vid = (j < 68) ? keyindex[j] : ridx_w[j - 68];
            srw[l] = 3 * vid + c;
        }
        __syncthreads();
        float a1 = 0.f, a2 = 0.f;
        const int c1 = lane;
        const int c2 = lane + 32;
#pragma unroll 2
        for (int rr = wid; rr < 600; rr += 16) {
            size_t r = (size_t)srw[rr];
            float v1 = w_shp[r * 40 + c1];
            a1 += v1 * v1;
            if (c2 < 50) {
                float v2 = (c2 < 40) ? w_shp[r * 40 + c2] : w_exp[r * 10 + (c2 - 40)];
                a2 += v2 * v2;
            }
        }
        cpart[wid][c1] = a1;
        if (c2 < 50) cpart[wid][c2] = a2;
        __syncthreads();
        if (tid < 50) {
            float s = 0.f;
#pragma unroll
            for (int w = 0; w < 16; w++) s += cpart[w][tid];
            g_wcol[tid] = sqrtf(s);
        }
        __threadfence();
        __syncthreads();
        if (tid == 0) atomicExch(&g_wflag, 1);
        return;
    }

    // ============ per-batch block ============
    const int n = blockIdx.x;

    extern __shared__ float S[];       // S[row*52 + c]: c0..49 = wshp|wexp, c50 = u, c51 pad
    __shared__ float sp[62], spg[62];
    __shared__ int   sidx[332];        // [0,68) key | [68,200) ridx_w | [200,332) ridx_v
    __shared__ int   srow[996];        // global row index (3*vid+cc) per S row
    __shared__ float bv[600], bvg[600];
    __shared__ float tn_w[16][3];
    __shared__ float tnsq[3];
    __shared__ float4 vt4[200], vtg4[200];   // .w = |xyz|^2
    __shared__ float wsum[16];
    __shared__ int   s_last;

    // ---- 0a. params + indices ----
    if (tid < 62) {
        float st = param_std[tid], mn = param_mean[tid];
        sp[tid]  = input [n * 62 + tid] * st + mn;
        spg[tid] = target[n * 62 + tid] * st + mn;
    } else if (tid >= 64 && tid < 396) {
        int j = tid - 64;
        sidx[j] = (j < 68) ? keyindex[j] : (j < 200 ? ridx_w[j - 68] : ridx_v[j - 200]);
    }
    __syncthreads();

    // ---- 0b. per-row global addresses ----
    // S rows: [0,204) keypoints | [204,600) ridx_v | [600,996) ridx_w
    for (int i = tid; i < 996; i += NT) {
        int vid, cc;
        if (i < 204)      { vid = sidx[i / 3];                       cc = i % 3; }
        else if (i < 600) { int m = i - 204; vid = sidx[200 + m / 3]; cc = m % 3; }
        else              { int m = i - 600; vid = sidx[68 + m / 3];  cc = m % 3; }
        srow[i] = 3 * vid + cc;
    }
    __syncthreads();

    // ---- 1. coalesced copy (warps 0..14) ; warp 15: normals column sums ----
    float ns0 = 0.f, ns1 = 0.f, ns2 = 0.f;
    if (wid < 15) {
        const int NTC = 480;
        const float4* w4 = (const float4*)w_shp;
#pragma unroll 2
        for (int e = tid; e < 9960; e += NTC) {
            int row = e / 10, f = e - 10 * row;
            float4 v = w4[(size_t)srow[row] * 10 + f];
            *(float4*)(S + row * 52 + 4 * f) = v;
        }
        const float2* e2 = (const float2*)w_exp;
#pragma unroll 2
        for (int e = tid; e < 4980; e += NTC) {
            int row = e / 5, f = e - 5 * row;
            float2 v = e2[(size_t)srow[row] * 5 + f];
            *(float2*)(S + row * 52 + 40 + 2 * f) = v;
        }
        for (int i = tid; i < 996; i += NTC) {
            S[i * 52 + 50] = u[srow[i]];
        }
    } else {
        const float* nb = normals + (size_t)n * (68 * 68);
#pragma unroll 4
        for (int i = 0; i < 68; i++) {
            const float* rowp = nb + i * 68;
            ns0 += rowp[lane];
            ns1 += rowp[lane + 32];
            if (lane < 4) ns2 += rowp[lane + 64];
        }
    }
    __syncthreads();

    // ---- 2. dot phase from SMEM: 996 row jobs (conflict-free LDS.128) ----
    float tn0 = 0.f, tn1 = 0.f, tn2 = 0.f;
#pragma unroll 1
    for (int l = tid; l < 996; l += NT) {
        const float4* Sr = (const float4*)(S + l * 52);
        if (l < 600) {
            // dual pred+gt
            float pa = 0.f, pb = 0.f, ga = 0.f, gb = 0.f;
#pragma unroll
            for (int f = 0; f < 12; f++) {
                float4 x = Sr[f];
                pa += x.x * sp [12 + 4*f] + x.z * sp [14 + 4*f];
                pb += x.y * sp [13 + 4*f] + x.w * sp [15 + 4*f];
                ga += x.x * spg[12 + 4*f] + x.z * spg[14 + 4*f];
                gb += x.y * spg[13 + 4*f] + x.w * spg[15 + 4*f];
            }
            float4 t = Sr[12];           // x=col48, y=col49, z=u, w=pad
            pa += t.x * sp [60] + t.z;   pb += t.y * sp [61];
            ga += t.x * spg[60] + t.z;   gb += t.y * spg[61];
            float s = pa + pb, g = ga + gb;
            bv[l] = s; bvg[l] = g;
            if (l < 204) {
                float s2 = s * s;
                int c3 = l % 3;
                if (c3 == 0) tn0 += s2; else if (c3 == 1) tn1 += s2; else tn2 += s2;
            }
        } else {
            // pred-only (ridx_w rows) -> tn
            float pa = 0.f, pb = 0.f;
#pragma unroll
            for (int f = 0; f < 12; f++) {
                float4 x = Sr[f];
                pa += x.x * sp[12 + 4*f] + x.z * sp[14 + 4*f];
                pb += x.y * sp[13 + 4*f] + x.w * sp[15 + 4*f];
            }
            float4 t = Sr[12];
            pa += t.x * sp[60] + t.z;
            pb += t.y * sp[61];
            float s = pa + pb;
            float s2 = s * s;
            int c3 = l % 3;
            if (c3 == 0) tn0 += s2; else if (c3 == 1) tn1 += s2; else tn2 += s2;
        }
    }
    tn0 = warp_sum(tn0); tn1 = warp_sum(tn1); tn2 = warp_sum(tn2);
    if (lane == 0) { tn_w[wid][0] = tn0; tn_w[wid][1] = tn1; tn_w[wid][2] = tn2; }
    __syncthreads();

    // ---- 3. fold tn, rotate verts (+|v|^2 in .w), wait for wcol flag ----
    if (tid < 3) {
        float s = 0.f;
#pragma unroll
        for (int w = 0; w < 16; w++) s += tn_w[w][tid];
        tnsq[tid] = s;
    }
    if (tid >= 256 && tid < 456) {
        int t = tid - 256;
        float b0 = bv [3*t], b1 = bv [3*t+1], b2 = bv [3*t+2];
        float c0 = bvg[3*t], c1 = bvg[3*t+1], c2 = bvg[3*t+2];
        float4 o1, o2;
        o1.x = sp [0]*b0 + sp [1]*b1 + sp [2]*b2 + sp [3];
        o1.y = sp [4]*b0 + sp [5]*b1 + sp [6]*b2 + sp [7];
        o1.z = sp [8]*b0 + sp [9]*b1 + sp[10]*b2 + sp[11];
        o1.w = o1.x*o1.x + o1.y*o1.y + o1.z*o1.z;
        o2.x = spg[0]*c0 + spg[1]*c1 + spg[2]*c2 + spg[3];
        o2.y = spg[4]*c0 + spg[5]*c1 + spg[6]*c2 + spg[7];
        o2.z = spg[8]*c0 + spg[9]*c1 + spg[10]*c2 + spg[11];
        o2.w = o2.x*o2.x + o2.y*o2.y + o2.z*o2.z;
        vt4[t] = o1; vtg4[t] = o2;
    }
    if (tid == 32) {
        while (atomicAdd(&g_wflag, 0) == 0) __nanosleep(64);
    }
    __syncthreads();
    __threadfence();  // acquire for g_wcol

    // ---- 4. warp0: weights+wpdc; chamfer on 400 threads (1 query each); warp 15: nwl ----
    float tot = 0.f;
    if (wid == 0) {
        int p1 = lane, p2 = lane + 32;
        float wj1, wj2 = 0.f;
        {
            float pd = fabsf(sp[p1] - spg[p1]);
            if (p1 < 11) {
                int cc = p1 & 3;
                float sc = (cc < 3) ? sqrtf(tnsq[cc]) : 14.142135623730951f;
                wj1 = pd * sc + 1e-6f;
            } else if (p1 == 11) wj1 = 1e-6f;
            else wj1 = 0.00057339936f * pd * g_wcol[p1 - 12] + 1e-6f;
        }
        if (p2 < 62) {
            float pd = fabsf(sp[p2] - spg[p2]);
            wj2 = 0.00057339936f * pd * g_wcol[p2 - 12] + 1e-6f;
        }
        float m = fmaxf(wj1, wj2);
#pragma unroll
        for (int o = 16; o; o >>= 1) m = fmaxf(m, __shfl_xor_sync(0xffffffffu, m, o));
        float wpdc = 0.f;
        if (p1 != 11) {
            float d = input[n * 62 + p1] - target[n * 62 + p1];
            wpdc += (wj1 / m) * d * d;
        }
        if (p2 < 62) {
            float d = input[n * 62 + p2] - target[n * 62 + p2];
            wpdc += (wj2 / m) * d * d;
        }
        tot += wpdc * (1.f / (128.f * 62.f));
    } else if (tid >= 64 && tid < 264) {
        // chamfer dir-1: one gt query per thread vs pred set. d2 = X.w + min_k(a.w - 2 X.a)
        int t = tid - 64;
        float4 X = vtg4[t];
        float xx = -2.f*X.x, xy = -2.f*X.y, xz = -2.f*X.z;
        float ma = 3.4e38f, mb = 3.4e38f;
#pragma unroll 4
        for (int k = 0; k < 200; k += 2) {
            float4 a = vt4[k], b = vt4[k + 1];
            ma = fminf(ma, fmaf(xx, a.x, fmaf(xy, a.y, fmaf(xz, a.z, a.w))));
            mb = fminf(mb, fmaf(xx, b.x, fmaf(xy, b.y, fmaf(xz, b.z, b.w))));
        }
        tot += (X.w + fminf(ma, mb)) * (3.f * 0.001f / (128.f * 200.f));
    } else if (tid >= 264 && tid < 464) {
        // chamfer dir-2: one pred query per thread vs gt set
        int t = tid - 264;
        float4 Y = vt4[t];
        float yx = -2.f*Y.x, yy = -2.f*Y.y, yz = -2.f*Y.z;
        float ma = 3.4e38f, mb = 3.4e38f;
#pragma unroll 4
        for (int k = 0; k < 200; k += 2) {
            float4 a = vtg4[k], b = vtg4[k + 1];
            ma = fminf(ma, fmaf(yx, a.x, fmaf(yy, a.y, fmaf(yz, a.z, a.w))));
            mb = fminf(mb, fmaf(yx, b.x, fmaf(yy, b.y, fmaf(yz, b.z, b.w))));
        }
        tot += (Y.w + fminf(ma, mb)) * (3.f * 0.001f / (128.f * 200.f));
    } else if (wid == 15) {
        const float k_nwl = 3.f * 0.001f / (128.f * 68.f * 3.f);
        {
            int t = lane;
            float d0 = vtg4[t].x - vt4[t].x;
            float d1 = vtg4[t].y - vt4[t].y;
            float d2 = vtg4[t].z - vt4[t].z;
            tot += ns0 * (d0*d0 + d1*d1 + d2*d2) * k_nwl;
        }
        {
            int t = lane + 32;
            float d0 = vtg4[t].x - vt4[t].x;
            float d1 = vtg4[t].y - vt4[t].y;
            float d2 = vtg4[t].z - vt4[t].z;
            tot += ns1 * (d0*d0 + d1*d1 + d2*d2) * k_nwl;
        }
        if (lane < 4) {
            int t = lane + 64;
            float d0 = vtg4[t].x - vt4[t].x;
            float d1 = vtg4[t].y - vt4[t].y;
            float d2 = vtg4[t].z - vt4[t].z;
            tot += ns2 * (d0*d0 + d1*d1 + d2*d2) * k_nwl;
        }
    }

    // ---- 5. block reduce + finalize (fixed order -> deterministic) ----
    tot = warp_sum(tot);
    if (lane == 0) wsum[wid] = tot;
    __syncthreads();
    if (tid == 0) {
        float b = 0.f;
#pragma unroll
        for (int w = 0; w < 16; w++) b += wsum[w];
        g_partials[n] = b;
        __threadfence();
        unsigned int old = atomicAdd(&g_count, 1u);
        s_last = (old == BATCH - 1);
    }
    __syncthreads();
    if (s_last) {
        __threadfence();
        if (wid == 0) {
            float v = g_partials[lane] + g_partials[lane + 32]
                    + g_partials[lane + 64] + g_partials[lane + 96];
#pragma unroll
            for (int o = 16; o; o >>= 1) v += __shfl_down_sync(0xffffffffu, v, o);
            if (lane == 0) { out[0] = v; g_count = 0; g_wflag = 0; }
        }
    }
}

extern "C" void kernel_launch(void* const* d_in, const int* in_sizes, int n_in,
                              void* d_out, int out_size)
{
    (void)in_sizes; (void)n_in; (void)out_size;
    cudaFuncSetAttribute(loss_main, cudaFuncAttributeMaxDynamicSharedMemorySize, S_BYTES);
    loss_main<<<BATCH + 1, NT, S_BYTES>>>(
        (const float*)d_in[0],   // input
        (const float*)d_in[1],   // target
        (const float*)d_in[2],   // normals
        (const float*)d_in[3],   // param_mean
        (const float*)d_in[4],   // param_std
        (const float*)d_in[5],   // u
        (const float*)d_in[6],   // w_shp
        (const float*)d_in[7],   // w_exp
        (const int*)d_in[8],     // keyindex
        (const int*)d_in[9],     // resample_idx_w
        (const int*)d_in[10],    // resample_idx_v
        (float*)d_out);
}

// round 15
// speedup vs baseline: 1.1074x; 1.0828x over previous
#include <cuda_runtime.h>

#define BATCH 128
#define NT 512
#define S_BYTES (996 * 52 * 4)

__device__ float g_partials[BATCH];
__device__ float g_wcol[50];
__device__ unsigned int g_count = 0;
__device__ int g_wflag = 0;

__device__ __forceinline__ float warp_sum(float v) {
#pragma unroll
    for (int o = 16; o; o >>= 1) v += __shfl_down_sync(0xffffffffu, v, o);
    return v;
}

// grid = BATCH+1. Blocks 0..127: one batch element. Block 128: w_cat column norms.
__global__ __launch_bounds__(NT, 1)
void loss_main(const float* __restrict__ input,
               const float* __restrict__ target,
               const float* __restrict__ normals,
               const float* __restrict__ param_mean,
               const float* __restrict__ param_std,
               const float* __restrict__ u,
               const float* __restrict__ w_shp,
               const float* __restrict__ w_exp,
               const int*   __restrict__ keyindex,
               const int*   __restrict__ ridx_w,
               const int*   __restrict__ ridx_v,
               float* __restrict__ out)
{
    const int tid  = threadIdx.x;
    const int lane = tid & 31;
    const int wid  = tid >> 5;

    // ============ dedicated block: batch-independent w_cat column norms ============
    if (blockIdx.x == BATCH) {
        __shared__ int srw[600];
        __shared__ float cpart[16][50];
        for (int l = tid; l < 600; l += NT) {
            int j = l / 3, c = l - 3 * j;
            int vid = (j < 68) ? keyindex[j] : ridx_w[j - 68];
            srw[l] = 3 * vid + c;
        }
        __syncthreads();
        float a1 = 0.f, a2 = 0.f;
        const int c1 = lane;
        const int c2 = lane + 32;
#pragma unroll 2
        for (int rr = wid; rr < 600; rr += 16) {
            size_t r = (size_t)srw[rr];
            float v1 = w_shp[r * 40 + c1];
            a1 += v1 * v1;
            if (c2 < 50) {
                float v2 = (c2 < 40) ? w_shp[r * 40 + c2] : w_exp[r * 10 + (c2 - 40)];
                a2 += v2 * v2;
            }
        }
        cpart[wid][c1] = a1;
        if (c2 < 50) cpart[wid][c2] = a2;
        __syncthreads();
        if (tid < 50) {
            float s = 0.f;
#pragma unroll
            for (int w = 0; w < 16; w++) s += cpart[w][tid];
            g_wcol[tid] = sqrtf(s);
        }
        __threadfence();
        __syncthreads();
        if (tid == 0) atomicExch(&g_wflag, 1);
        return;
    }

    // ============ per-batch block ============
    const int n = blockIdx.x;

    extern __shared__ float S[];       // S[row*52 + c]: c0..49 = wshp|wexp, c50 = u, c51 pad
    __shared__ float sp[62], spg[62];
    __shared__ int   sidx[332];        // [0,68) key | [68,200) ridx_w | [200,332) ridx_v
    __shared__ int   srow[996];        // global row index (3*vid+cc) per S row
    __shared__ float bv[600], bvg[600];
    __shared__ float tn_w[16][3];
    __shared__ float tnsq[3];
    __shared__ float4 vt4[200], vtg4[200];   // .w = |xyz|^2
    __shared__ float wsum[16];
    __shared__ int   s_last;

    // ---- 0a. params + indices ----
    if (tid < 62) {
        float st = param_std[tid], mn = param_mean[tid];
        sp[tid]  = input [n * 62 + tid] * st + mn;
        spg[tid] = target[n * 62 + tid] * st + mn;
    } else if (tid >= 64 && tid < 396) {
        int j = tid - 64;
        sidx[j] = (j < 68) ? keyindex[j] : (j < 200 ? ridx_w[j - 68] : ridx_v[j - 200]);
    }
    __syncthreads();

    // ---- 0b. per-row global addresses ----
    // S rows: [0,204) keypoints | [204,600) ridx_v | [600,996) ridx_w
    for (int i = tid; i < 996; i += NT) {
        int vid, cc;
        if (i < 204)      { vid = sidx[i / 3];                       cc = i % 3; }
        else if (i < 600) { int m = i - 204; vid = sidx[200 + m / 3]; cc = m % 3; }
        else              { int m = i - 600; vid = sidx[68 + m / 3];  cc = m % 3; }
        srow[i] = 3 * vid + cc;
    }
    __syncthreads();

    // ---- 1. coalesced copy (warps 0..14) ; warp 15: normals column sums ----
    float ns0 = 0.f, ns1 = 0.f, ns2 = 0.f;
    if (wid < 15) {
        const int NTC = 480;
        const float4* w4 = (const float4*)w_shp;
#pragma unroll 2
        for (int e = tid; e < 9960; e += NTC) {
            int row = e / 10, f = e - 10 * row;
            float4 v = w4[(size_t)srow[row] * 10 + f];
            *(float4*)(S + row * 52 + 4 * f) = v;
        }
        const float2* e2 = (const float2*)w_exp;
#pragma unroll 2
        for (int e = tid; e < 4980; e += NTC) {
            int row = e / 5, f = e - 5 * row;
            float2 v = e2[(size_t)srow[row] * 5 + f];
            *(float2*)(S + row * 52 + 40 + 2 * f) = v;
        }
        for (int i = tid; i < 996; i += NTC) {
            S[i * 52 + 50] = u[srow[i]];
        }
    } else {
        const float* nb = normals + (size_t)n * (68 * 68);
#pragma unroll 4
        for (int i = 0; i < 68; i++) {
            const float* rowp = nb + i * 68;
            ns0 += rowp[lane];
            ns1 += rowp[lane + 32];
            if (lane < 4) ns2 += rowp[lane + 64];
        }
    }
    __syncthreads();

    // ---- 2. dot phase from SMEM: 996 row jobs (conflict-free LDS.128) ----
    float tn0 = 0.f, tn1 = 0.f, tn2 = 0.f;
#pragma unroll 1
    for (int l = tid; l < 996; l += NT) {
        const float4* Sr = (const float4*)(S + l * 52);
        if (l < 600) {
            // dual pred+gt
            float pa = 0.f, pb = 0.f, ga = 0.f, gb = 0.f;
#pragma unroll
            for (int f = 0; f < 12; f++) {
                float4 x = Sr[f];
                pa += x.x * sp [12 + 4*f] + x.z * sp [14 + 4*f];
                pb += x.y * sp [13 + 4*f] + x.w * sp [15 + 4*f];
                ga += x.x * spg[12 + 4*f] + x.z * spg[14 + 4*f];
                gb += x.y * spg[13 + 4*f] + x.w * spg[15 + 4*f];
            }
            float4 t = Sr[12];           // x=col48, y=col49, z=u, w=pad
            pa += t.x * sp [60] + t.z;   pb += t.y * sp [61];
            ga += t.x * spg[60] + t.z;   gb += t.y * spg[61];
            float s = pa + pb, g = ga + gb;
            bv[l] = s; bvg[l] = g;
            if (l < 204) {
                float s2 = s * s;
                int c3 = l % 3;
                if (c3 == 0) tn0 += s2; else if (c3 == 1) tn1 += s2; else tn2 += s2;
            }
        } else {
            // pred-only (ridx_w rows) -> tn
            float pa = 0.f, pb = 0.f;
#pragma unroll
            for (int f = 0; f < 12; f++) {
                float4 x = Sr[f];
                pa += x.x * sp[12 + 4*f] + x.z * sp[14 + 4*f];
                pb += x.y * sp[13 + 4*f] + x.w * sp[15 + 4*f];
            }
            float4 t = Sr[12];
            pa += t.x * sp[60] + t.z;
            pb += t.y * sp[61];
            float s = pa + pb;
            float s2 = s * s;
            int c3 = l % 3;
            if (c3 == 0) tn0 += s2; else if (c3 == 1) tn1 += s2; else tn2 += s2;
        }
    }
    tn0 = warp_sum(tn0); tn1 = warp_sum(tn1); tn2 = warp_sum(tn2);
    if (lane == 0) { tn_w[wid][0] = tn0; tn_w[wid][1] = tn1; tn_w[wid][2] = tn2; }
    __syncthreads();

    // ---- 3. fold tn, rotate verts (+|v|^2 in .w), wait for wcol flag ----
    if (tid < 3) {
        float s = 0.f;
#pragma unroll
        for (int w = 0; w < 16; w++) s += tn_w[w][tid];
        tnsq[tid] = s;
    }
    if (tid >= 256 && tid < 456) {
        int t = tid - 256;
        float b0 = bv [3*t], b1 = bv [3*t+1], b2 = bv [3*t+2];
        float c0 = bvg[3*t], c1 = bvg[3*t+1], c2 = bvg[3*t+2];
        float4 o1, o2;
        o1.x = sp [0]*b0 + sp [1]*b1 + sp [2]*b2 + sp [3];
        o1.y = sp [4]*b0 + sp [5]*b1 + sp [6]*b2 + sp [7];
        o1.z = sp [8]*b0 + sp [9]*b1 + sp[10]*b2 + sp[11];
        o1.w = o1.x*o1.x + o1.y*o1.y + o1.z*o1.z;
        o2.x = spg[0]*c0 + spg[1]*c1 + spg[2]*c2 + spg[3];
        o2.y = spg[4]*c0 + spg[5]*c1 + spg[6]*c2 + spg[7];
        o2.z = spg[8]*c0 + spg[9]*c1 + spg[10]*c2 + spg[11];
        o2.w = o2.x*o2.x + o2.y*o2.y + o2.z*o2.z;
        vt4[t] = o1; vtg4[t] = o2;
    }
    if (tid == 32) {
        while (atomicAdd(&g_wflag, 0) == 0) __nanosleep(64);
    }
    __syncthreads();
    __threadfence();  // acquire for g_wcol

    // ---- 4. warp0: weights+wpdc; chamfer tid 96..195 & 256..355; warp 15: nwl ----
    float tot = 0.f;
    if (wid == 0) {
        int p1 = lane, p2 = lane + 32;
        float wj1, wj2 = 0.f;
        {
            float pd = fabsf(sp[p1] - spg[p1]);
            if (p1 < 11) {
                int cc = p1 & 3;
                float sc = (cc < 3) ? sqrtf(tnsq[cc]) : 14.142135623730951f;
                wj1 = pd * sc + 1e-6f;
            } else if (p1 == 11) wj1 = 1e-6f;
            else wj1 = 0.00057339936f * pd * g_wcol[p1 - 12] + 1e-6f;
        }
        if (p2 < 62) {
            float pd = fabsf(sp[p2] - spg[p2]);
            wj2 = 0.00057339936f * pd * g_wcol[p2 - 12] + 1e-6f;
        }
        float m = fmaxf(wj1, wj2);
#pragma unroll
        for (int o = 16; o; o >>= 1) m = fmaxf(m, __shfl_xor_sync(0xffffffffu, m, o));
        float wpdc = 0.f;
        if (p1 != 11) {
            float d = input[n * 62 + p1] - target[n * 62 + p1];
            wpdc += (wj1 / m) * d * d;
        }
        if (p2 < 62) {
            float d = input[n * 62 + p2] - target[n * 62 + p2];
            wpdc += (wj2 / m) * d * d;
        }
        tot += wpdc * (1.f / (128.f * 62.f));
    } else if (tid >= 96 && tid < 196) {
        int t = tid - 96;
        float4 X1 = vtg4[t], X2 = vtg4[t + 100];
        float x1x = -2.f*X1.x, x1y = -2.f*X1.y, x1z = -2.f*X1.z;
        float x2x = -2.f*X2.x, x2y = -2.f*X2.y, x2z = -2.f*X2.z;
        float m1a = 3.4e38f, m1b = 3.4e38f, m2a = 3.4e38f, m2b = 3.4e38f;
#pragma unroll 4
        for (int k = 0; k < 200; k += 2) {
            float4 a = vt4[k], b = vt4[k + 1];
            m1a = fminf(m1a, fmaf(x1x, a.x, fmaf(x1y, a.y, fmaf(x1z, a.z, a.w))));
            m1b = fminf(m1b, fmaf(x1x, b.x, fmaf(x1y, b.y, fmaf(x1z, b.z, b.w))));
            m2a = fminf(m2a, fmaf(x2x, a.x, fmaf(x2y, a.y, fmaf(x2z, a.z, a.w))));
            m2b = fminf(m2b, fmaf(x2x, b.x, fmaf(x2y, b.y, fmaf(x2z, b.z, b.w))));
        }
        float d1 = X1.w + fminf(m1a, m1b);
        float d2 = X2.w + fminf(m2a, m2b);
        tot += (d1 + d2) * (3.f * 0.001f / (128.f * 200.f));
    } else if (tid >= 256 && tid < 356) {
        int t = tid - 256;
        float4 Y1 = vt4[t], Y2 = vt4[t + 100];
        float y1x = -2.f*Y1.x, y1y = -2.f*Y1.y, y1z = -2.f*Y1.z;
        float y2x = -2.f*Y2.x, y2y = -2.f*Y2.y, y2z = -2.f*Y2.z;
        float m1a = 3.4e38f, m1b = 3.4e38f, m2a = 3.4e38f, m2b = 3.4e38f;
#pragma unroll 4
        for (int k = 0; k < 200; k += 2) {
            float4 a = vtg4[k], b = vtg4[k + 1];
            m1a = fminf(m1a, fmaf(y1x, a.x, fmaf(y1y, a.y, fmaf(y1z, a.z, a.w))));
            m1b = fminf(m1b, fmaf(y1x, b.x, fmaf(y1y, b.y, fmaf(y1z, b.z, b.w))));
            m2a = fminf(m2a, fmaf(y2x, a.x, fmaf(y2y, a.y, fmaf(y2z, a.z, a.w))));
            m2b = fminf(m2b, fmaf(y2x, b.x, fmaf(y2y, b.y, fmaf(y2z, b.z, b.w))));
        }
        float d1 = Y1.w + fminf(m1a, m1b);
        float d2 = Y2.w + fminf(m2a, m2b);
        tot += (d1 + d2) * (3.f * 0.001f / (128.f * 200.f));
    } else if (wid == 15) {
        const float k_nwl = 3.f * 0.001f / (128.f * 68.f * 3.f);
        {
            int t = lane;
            float d0 = vtg4[t].x - vt4[t].x;
            float d1 = vtg4[t].y - vt4[t].y;
            float d2 = vtg4[t].z - vt4[t].z;
            tot += ns0 * (d0*d0 + d1*d1 + d2*d2) * k_nwl;
        }
        {
            int t = lane + 32;
            float d0 = vtg4[t].x - vt4[t].x;
            float d1 = vtg4[t].y - vt4[t].y;
            float d2 = vtg4[t].z - vt4[t].z;
            tot += ns1 * (d0*d0 + d1*d1 + d2*d2) * k_nwl;
        }
        if (lane < 4) {
            int t = lane + 64;
            float d0 = vtg4[t].x - vt4[t].x;
            float d1 = vtg4[t].y - vt4[t].y;
            float d2 = vtg4[t].z - vt4[t].z;
            tot += ns2 * (d0*d0 + d1*d1 + d2*d2) * k_nwl;
        }
    }

    // ---- 5. block reduce + finalize (fixed order -> deterministic) ----
    tot = warp_sum(tot);
    if (lane == 0) wsum[wid] = tot;
    __syncthreads();
    if (tid == 0) {
        float b = 0.f;
#pragma unroll
        for (int w = 0; w < 16; w++) b += wsum[w];
        g_partials[n] = b;
        __threadfence();
        unsigned int old = atomicAdd(&g_count, 1u);
        s_last = (old == BATCH - 1);
    }
    __syncthreads();
    if (s_last) {
        __threadfence();
        if (wid == 0) {
            float v = g_partials[lane] + g_partials[lane + 32]
                    + g_partials[lane + 64] + g_partials[lane + 96];
#pragma unroll
            for (int o = 16; o; o >>= 1) v += __shfl_down_sync(0xffffffffu, v, o);
            if (lane == 0) { out[0] = v; g_count = 0; g_wflag = 0; }
        }
    }
}

extern "C" void kernel_launch(void* const* d_in, const int* in_sizes, int n_in,
                              void* d_out, int out_size)
{
    (void)in_sizes; (void)n_in; (void)out_size;
    cudaFuncSetAttribute(loss_main, cudaFuncAttributeMaxDynamicSharedMemorySize, S_BYTES);
    loss_main<<<BATCH + 1, NT, S_BYTES>>>(
        (const float*)d_in[0],   // input
        (const float*)d_in[1],   // target
        (const float*)d_in[2],   // normals
        (const float*)d_in[3],   // param_mean
        (const float*)d_in[4],   // param_std
        (const float*)d_in[5],   // u
        (const float*)d_in[6],   // w_shp
        (const float*)d_in[7],   // w_exp
        (const int*)d_in[8],     // keyindex
        (const int*)d_in[9],     // resample_idx_w
        (const int*)d_in[10],    // resample_idx_v
        (float*)d_out);
}